// round 1
// baseline (speedup 1.0000x reference)
#include <cuda_runtime.h>

#define NB     512
#define NU_PTS 32
#define NV_PTS 128
#define NC     16

__global__ __launch_bounds__(256, 4)
void surf_eval_kernel(const float4* __restrict__ ctrl,   // [NB][16][16] of (x,y,z,w)
                      const float4* __restrict__ Nu4,    // [32]
                      const float4* __restrict__ Nv4,    // [128]
                      const int*    __restrict__ uspan,  // [32]
                      const int*    __restrict__ vspan,  // [128]
                      float*        __restrict__ out)    // [NB][32][128][3]
{
    __shared__ float4 sctrl[NC][NC];        // 4 KB  : control points for this batch
    __shared__ float4 sT[NC][NV_PTS];       // 32 KB : T[ui][v] = sum_j Nv[v,j]*ctrl[ui, vs+j]
    __shared__ float4 sNu[NU_PTS];
    __shared__ float4 sNv[NV_PTS];
    __shared__ int    sUs[NU_PTS];
    __shared__ int    sVs[NV_PTS];

    const int tid = threadIdx.x;
    const int b   = blockIdx.x;

    // ---- load: ctrl tile (256 float4, one per thread), basis + spans ----
    ((float4*)sctrl)[tid] = ctrl[b * 256 + tid];
    if (tid < NV_PTS) {
        sNv[tid] = Nv4[tid];
        sVs[tid] = vspan[tid] - 3;
    } else if (tid < NV_PTS + NU_PTS) {
        int u = tid - NV_PTS;
        sNu[u] = Nu4[u];
        sUs[u] = uspan[u] - 3;
    }
    __syncthreads();

    // ---- stage 1: contract over vj (4 sparse terms) ----
    // 16 ui rows x 128 v = 2048 outputs, 256 threads -> 8 iterations
    #pragma unroll
    for (int it = 0; it < 8; ++it) {
        int idx = it * 256 + tid;
        int ui  = idx >> 7;        // 0..15
        int v   = idx & 127;       // 0..127
        int vs  = sVs[v];
        float4 nv = sNv[v];
        float4 c0 = sctrl[ui][vs + 0];
        float4 c1 = sctrl[ui][vs + 1];
        float4 c2 = sctrl[ui][vs + 2];
        float4 c3 = sctrl[ui][vs + 3];
        float4 t;
        t.x = nv.x * c0.x + nv.y * c1.x + nv.z * c2.x + nv.w * c3.x;
        t.y = nv.x * c0.y + nv.y * c1.y + nv.z * c2.y + nv.w * c3.y;
        t.z = nv.x * c0.z + nv.y * c1.z + nv.z * c2.z + nv.w * c3.z;
        t.w = nv.x * c0.w + nv.y * c1.w + nv.z * c2.w + nv.w * c3.w;
        sT[ui][v] = t;
    }
    __syncthreads();

    // ---- stage 2: contract over ui (4 sparse terms), divide, store ----
    // 32 u x 128 v = 4096 points, 256 threads -> 16 iterations (2 u-rows each)
    #pragma unroll
    for (int it = 0; it < 16; ++it) {
        int u  = it * 2 + (tid >> 7);  // 0..31
        int v  = tid & 127;
        int i0 = sUs[u];
        float4 nu = sNu[u];
        float4 t0 = sT[i0 + 0][v];
        float4 t1 = sT[i0 + 1][v];
        float4 t2 = sT[i0 + 2][v];
        float4 t3 = sT[i0 + 3][v];
        float x = nu.x * t0.x + nu.y * t1.x + nu.z * t2.x + nu.w * t3.x;
        float y = nu.x * t0.y + nu.y * t1.y + nu.z * t2.y + nu.w * t3.y;
        float z = nu.x * t0.z + nu.y * t1.z + nu.z * t2.z + nu.w * t3.z;
        float w = nu.x * t0.w + nu.y * t1.w + nu.z * t2.w + nu.w * t3.w;

        float r = __fdividef(1.0f, fmaxf(w, 1e-8f));
        int o = ((b * NU_PTS + u) * NV_PTS + v) * 3;
        out[o + 0] = x * r;
        out[o + 1] = y * r;
        out[o + 2] = z * r;
    }
}

extern "C" void kernel_launch(void* const* d_in, const int* in_sizes, int n_in,
                              void* d_out, int out_size)
{
    const float4* ctrl  = (const float4*)d_in[0];
    const float4* Nu4   = (const float4*)d_in[1];
    const float4* Nv4   = (const float4*)d_in[2];
    const int*    uspan = (const int*)d_in[3];
    const int*    vspan = (const int*)d_in[4];
    float*        out   = (float*)d_out;

    surf_eval_kernel<<<NB, 256>>>(ctrl, Nu4, Nv4, uspan, vspan, out);
}

// round 2
// speedup vs baseline: 1.1891x; 1.1891x over previous
#include <cuda_runtime.h>

#define NB     512
#define NU_PTS 32
#define NV_PTS 128
#define NC     16

__global__ __launch_bounds__(256, 4)
void surf_eval_kernel(const float4* __restrict__ ctrl,   // [NB][16][16] of (x,y,z,w)
                      const float4* __restrict__ Nu4,    // [32]
                      const float4* __restrict__ Nv4,    // [128]
                      const int*    __restrict__ uspan,  // [32]
                      const int*    __restrict__ vspan,  // [128]
                      float*        __restrict__ out)    // [NB][32][128][3]
{
    __shared__ float4 sctrl[NC][NC];        // 4 KB
    __shared__ float4 sT[NC][NV_PTS];       // 32 KB : T[ui][v] = sum_j Nv[v,j]*ctrl[ui, vs+j]
    __shared__ float4 sNu[NU_PTS];
    __shared__ float4 sNv[NV_PTS];
    __shared__ int    sUs[NU_PTS];
    __shared__ int    sVs[NV_PTS];

    const int tid = threadIdx.x;
    const int b   = blockIdx.x;

    // ---- load: ctrl tile (256 float4), basis + spans ----
    ((float4*)sctrl)[tid] = ctrl[b * 256 + tid];
    if (tid < NV_PTS) {
        sNv[tid] = Nv4[tid];
        sVs[tid] = vspan[tid] - 3;
    } else if (tid < NV_PTS + NU_PTS) {
        int u = tid - NV_PTS;
        sNu[u] = Nu4[u];
        sUs[u] = uspan[u] - 3;
    }
    __syncthreads();

    // ---- stage 1: contract over vj (4 sparse terms) ----
    #pragma unroll
    for (int it = 0; it < 8; ++it) {
        int idx = it * 256 + tid;
        int ui  = idx >> 7;        // 0..15
        int v   = idx & 127;       // 0..127
        int vs  = sVs[v];
        float4 nv = sNv[v];
        float4 c0 = sctrl[ui][vs + 0];
        float4 c1 = sctrl[ui][vs + 1];
        float4 c2 = sctrl[ui][vs + 2];
        float4 c3 = sctrl[ui][vs + 3];
        float4 t;
        t.x = nv.x * c0.x + nv.y * c1.x + nv.z * c2.x + nv.w * c3.x;
        t.y = nv.x * c0.y + nv.y * c1.y + nv.z * c2.y + nv.w * c3.y;
        t.z = nv.x * c0.z + nv.y * c1.z + nv.z * c2.z + nv.w * c3.z;
        t.w = nv.x * c0.w + nv.y * c1.w + nv.z * c2.w + nv.w * c3.w;
        sT[ui][v] = t;
    }
    __syncthreads();

    // ---- stage 2: rotating register window over sT rows ----
    // thread -> (v = tid&127, u-half = tid>>7 : u in [half*16, half*16+16) )
    // uspan is monotone in u and identical across lanes of a warp, so the
    // window-shift loop below is warp-uniform (no divergence), and each
    // sT row is loaded exactly ONCE per thread instead of 4x per point.
    {
        const int v    = tid & 127;
        const int half = tid >> 7;           // uniform within a warp
        const int u0   = half * 16;

        int r = sUs[u0];                      // current window base row
        float4 t0 = sT[r + 0][v];
        float4 t1 = sT[r + 1][v];
        float4 t2 = sT[r + 2][v];
        float4 t3 = sT[r + 3][v];

        #pragma unroll
        for (int k = 0; k < 16; ++k) {
            const int u  = u0 + k;
            const int i0 = sUs[u];
            while (r < i0) {                  // warp-uniform shift (0 or 1 typical)
                t0 = t1; t1 = t2; t2 = t3;
                t3 = sT[r + 4][v];
                ++r;
            }
            float4 nu = sNu[u];
            float x = nu.x * t0.x + nu.y * t1.x + nu.z * t2.x + nu.w * t3.x;
            float y = nu.x * t0.y + nu.y * t1.y + nu.z * t2.y + nu.w * t3.y;
            float z = nu.x * t0.z + nu.y * t1.z + nu.z * t2.z + nu.w * t3.z;
            float w = nu.x * t0.w + nu.y * t1.w + nu.z * t2.w + nu.w * t3.w;

            float rcp = __fdividef(1.0f, fmaxf(w, 1e-8f));
            int o = ((b * NU_PTS + u) * NV_PTS + v) * 3;
            out[o + 0] = x * rcp;
            out[o + 1] = y * rcp;
            out[o + 2] = z * rcp;
        }
    }
}

extern "C" void kernel_launch(void* const* d_in, const int* in_sizes, int n_in,
                              void* d_out, int out_size)
{
    const float4* ctrl  = (const float4*)d_in[0];
    const float4* Nu4   = (const float4*)d_in[1];
    const float4* Nv4   = (const float4*)d_in[2];
    const int*    uspan = (const int*)d_in[3];
    const int*    vspan = (const int*)d_in[4];
    float*        out   = (float*)d_out;

    surf_eval_kernel<<<NB, 256>>>(ctrl, Nu4, Nv4, uspan, vspan, out);
}